// round 10
// baseline (speedup 1.0000x reference)
#include <cuda_runtime.h>
#include <cuda_bf16.h>
#include <math.h>
#include <stdint.h>

#define NB 8
#define LSEQ 2048
#define CDIM 512
#define HDIM 512
#define CHALF 256
typedef __nv_bfloat16 bf16;

// ---------------- scratch (device globals: allocation-guard safe) ----------
__device__ __align__(1024) bf16 g_xb   [(size_t)NB * LSEQ * CDIM];
__device__ __align__(1024) bf16 g_wcat [3 * HDIM * CDIM];          // [1536,512]
__device__ __align__(1024) float g_bcat[3 * HDIM];                 // [1536]
__device__ __align__(1024) bf16 g_wr1T [CHALF * HDIM];
__device__ __align__(1024) bf16 g_wr2T [CDIM * CHALF];
__device__ __align__(1024) bf16 g_proj [(size_t)NB * LSEQ * 3 * HDIM]; // [16384,1536] xt|xph|xpsi
__device__ __align__(1024) bf16 g_xpsiT[(size_t)NB * HDIM * LSEQ];
__device__ __align__(1024) float g_S   [(size_t)NB * LSEQ * LSEQ]; // fp32 logits
__device__ __align__(1024) bf16 g_P    [(size_t)NB * LSEQ * LSEQ]; // bf16 attention
__device__ __align__(1024) bf16 g_xadd [(size_t)NB * LSEQ * HDIM];
__device__ __align__(1024) bf16 g_h1   [(size_t)NB * LSEQ * CHALF];

// smem: A stages 0/10240/20480, B stages 30720/40960/51200 (rows 80B pitch)
#define GEMM_SMEM 61440

// ---------------- asm helpers ------------------------------------------------
__device__ __forceinline__ void cp16(uint32_t dst, const void* src) {
    asm volatile("cp.async.cg.shared.global [%0], [%1], 16;"
                 :: "r"(dst), "l"(src) : "memory");
}
#define CP_COMMIT() asm volatile("cp.async.commit_group;" ::: "memory")
#define CP_WAIT1()  asm volatile("cp.async.wait_group 1;" ::: "memory")
#define CP_WAIT0()  asm volatile("cp.async.wait_group 0;" ::: "memory")

__device__ __forceinline__ void ldsm4(uint32_t* r, uint32_t addr) {
    asm volatile("ldmatrix.sync.aligned.m8n8.x4.shared.b16 {%0,%1,%2,%3}, [%4];"
                 : "=r"(r[0]), "=r"(r[1]), "=r"(r[2]), "=r"(r[3]) : "r"(addr));
}
__device__ __forceinline__ void mma_bf16(float* c, const uint32_t* a, const uint32_t* b) {
    asm volatile("mma.sync.aligned.m16n8k16.row.col.f32.bf16.bf16.f32 "
                 "{%0,%1,%2,%3},{%4,%5,%6,%7},{%8,%9},{%0,%1,%2,%3};"
                 : "+f"(c[0]), "+f"(c[1]), "+f"(c[2]), "+f"(c[3])
                 : "r"(a[0]), "r"(a[1]), "r"(a[2]), "r"(a[3]), "r"(b[0]), "r"(b[1]));
}

// ---------------- universal bf16 tensor-core GEMM ----------------------------
// C[M,N] = A[M,K] @ Bt[N,K]^T (+bias). Tile 128x128, BK=32, 3-stage cp.async.
// lda/ldb/ldc: row strides (elements). Batch via blockIdx.z with sA/sB/sC.
// EPI: 0 bias->bf16 | 2 fp32 | 3 bf16 | 4 bias+leaky->bf16 | 5 bias+tanh+res->fp32
template <int EPI>
__global__ void __launch_bounds__(256)
gemm5(const bf16* __restrict__ A, const bf16* __restrict__ Bt,
      const float* __restrict__ bias, const float* __restrict__ res,
      void* __restrict__ Cout, int K, int lda, int ldb, int ldc,
      long sA, long sB, long sC)
{
    extern __shared__ __align__(1024) char smem[];
    uint32_t sbase = (uint32_t)__cvta_generic_to_shared(smem);
    const int tid = threadIdx.x, wid = tid >> 5, lane = tid & 31;

    A  += (long)blockIdx.z * sA;
    Bt += (long)blockIdx.z * sB;
    const int m0 = blockIdx.y * 128, n0 = blockIdx.x * 128;

    const int wm = wid >> 2, wn = wid & 3;        // 2x4 warp grid
    const int m_off = wm * 64, n_off = wn * 32;

    float acc[4][4][4];
#pragma unroll
    for (int i = 0; i < 4; i++)
#pragma unroll
        for (int j = 0; j < 4; j++)
#pragma unroll
            for (int u = 0; u < 4; u++) acc[i][j][u] = 0.f;

    const int KT = K >> 5;
    auto ldA = [&](int kt, int buf) {
#pragma unroll
        for (int s = 0; s < 2; s++) {
            int ch = s * 256 + tid;
            int r = ch >> 2, seg = ch & 3;
            cp16(sbase + buf * 10240u + r * 80u + seg * 16u,
                 A + (long)(m0 + r) * lda + kt * 32 + seg * 8);
        }
    };
    auto ldB = [&](int kt, int buf) {
#pragma unroll
        for (int s = 0; s < 2; s++) {
            int ch = s * 256 + tid;
            int r = ch >> 2, seg = ch & 3;
            cp16(sbase + 30720u + buf * 10240u + r * 80u + seg * 16u,
                 Bt + (long)(n0 + r) * ldb + kt * 32 + seg * 8);
        }
    };

    ldA(0, 0); ldB(0, 0); CP_COMMIT();
    ldA(1, 1); ldB(1, 1); CP_COMMIT();

    // ldmatrix lane addressing (constant across k-steps)
    const int a_row = m_off + (lane & 15);
    const int a_kof = (lane >> 4) * 8;
    const int b_row = n_off + (lane & 7) + ((lane >> 4) & 1) * 8;
    const int b_kof = ((lane >> 3) & 1) * 8;

    int buf = 0;
    for (int kt = 0; kt < KT; kt++) {
        if (kt + 1 < KT) CP_WAIT1(); else CP_WAIT0();
        __syncthreads();
        if (kt + 2 < KT) {
            int nb = buf + 2; if (nb >= 3) nb -= 3;
            ldA(kt + 2, nb); ldB(kt + 2, nb);
            CP_COMMIT();
        }
        const uint32_t Ab = sbase + buf * 10240u;
        const uint32_t Bb = sbase + 30720u + buf * 10240u;
#pragma unroll
        for (int kk = 0; kk < 32; kk += 16) {
            uint32_t a[4][4], bq[2][4];
#pragma unroll
            for (int mt = 0; mt < 4; mt++)
                ldsm4(a[mt], Ab + ((a_row + mt * 16) * 40 + kk + a_kof) * 2);
#pragma unroll
            for (int p = 0; p < 2; p++)
                ldsm4(bq[p], Bb + ((b_row + p * 16) * 40 + kk + b_kof) * 2);
#pragma unroll
            for (int mt = 0; mt < 4; mt++)
#pragma unroll
                for (int nt = 0; nt < 4; nt++)
                    mma_bf16(acc[mt][nt], a[mt], &bq[nt >> 1][(nt & 1) * 2]);
        }
        if (++buf == 3) buf = 0;
    }

    // ---- epilogue ----
    const int l4 = lane >> 2, l2 = (lane & 3) * 2;
#pragma unroll
    for (int mt = 0; mt < 4; mt++) {
#pragma unroll
        for (int nt = 0; nt < 4; nt++) {
            int row = m0 + m_off + mt * 16 + l4;
            int col = n0 + n_off + nt * 8 + l2;
            float c0 = acc[mt][nt][0], c1 = acc[mt][nt][1];
            float c2 = acc[mt][nt][2], c3 = acc[mt][nt][3];
            if (EPI == 0 || EPI == 4 || EPI == 5) {
                float b0 = bias[col], b1 = bias[col + 1];
                c0 += b0; c1 += b1; c2 += b0; c3 += b1;
            }
            if (EPI == 4) {
                c0 = fmaxf(c0, 0.2f * c0); c1 = fmaxf(c1, 0.2f * c1);
                c2 = fmaxf(c2, 0.2f * c2); c3 = fmaxf(c3, 0.2f * c3);
            }
            if (EPI == 5) {
                const float2 r0 = *(const float2*)(res + (long)row * ldc + col);
                const float2 r1 = *(const float2*)(res + (long)(row + 8) * ldc + col);
                c0 = tanhf(c0) + r0.x; c1 = tanhf(c1) + r0.y;
                c2 = tanhf(c2) + r1.x; c3 = tanhf(c3) + r1.y;
            }
            if (EPI == 2 || EPI == 5) {
                float* Cf = (float*)Cout + (long)blockIdx.z * sC;
                *(float2*)(Cf + (long)row * ldc + col)       = make_float2(c0, c1);
                *(float2*)(Cf + (long)(row + 8) * ldc + col) = make_float2(c2, c3);
            } else {
                bf16* Cb = (bf16*)Cout + (long)blockIdx.z * sC;
                *(__nv_bfloat162*)(Cb + (long)row * ldc + col)       = __floats2bfloat162_rn(c0, c1);
                *(__nv_bfloat162*)(Cb + (long)(row + 8) * ldc + col) = __floats2bfloat162_rn(c2, c3);
            }
        }
    }
}

// ---------------- softmax: fp32 in -> bf16 out ------------------------------
__global__ void __launch_bounds__(256)
softmax_k(const float* __restrict__ S, bf16* __restrict__ P)
{
    long base = (long)blockIdx.x * LSEQ;
    const float4* S4 = (const float4*)(S + base);
    int tid = threadIdx.x;
    __shared__ float red[256];

    float4 v0 = S4[tid], v1 = S4[tid + 256];
    float m = fmaxf(fmaxf(fmaxf(v0.x, v0.y), fmaxf(v0.z, v0.w)),
                    fmaxf(fmaxf(v1.x, v1.y), fmaxf(v1.z, v1.w)));
    red[tid] = m;
    __syncthreads();
    for (int s = 128; s > 0; s >>= 1) {
        if (tid < s) red[tid] = fmaxf(red[tid], red[tid + s]);
        __syncthreads();
    }
    m = red[0];
    __syncthreads();

    v0.x = __expf(v0.x - m); v0.y = __expf(v0.y - m);
    v0.z = __expf(v0.z - m); v0.w = __expf(v0.w - m);
    v1.x = __expf(v1.x - m); v1.y = __expf(v1.y - m);
    v1.z = __expf(v1.z - m); v1.w = __expf(v1.w - m);
    float sum = (v0.x + v0.y + v0.z + v0.w) + (v1.x + v1.y + v1.z + v1.w);
    red[tid] = sum;
    __syncthreads();
    for (int s = 128; s > 0; s >>= 1) {
        if (tid < s) red[tid] += red[tid + s];
        __syncthreads();
    }
    float inv = 1.f / red[0];

    uint2* P2 = (uint2*)(P + base);
    __nv_bfloat162 a0 = __floats2bfloat162_rn(v0.x * inv, v0.y * inv);
    __nv_bfloat162 a1 = __floats2bfloat162_rn(v0.z * inv, v0.w * inv);
    __nv_bfloat162 b0 = __floats2bfloat162_rn(v1.x * inv, v1.y * inv);
    __nv_bfloat162 b1 = __floats2bfloat162_rn(v1.z * inv, v1.w * inv);
    P2[tid]       = make_uint2(*(uint32_t*)&a0, *(uint32_t*)&a1);
    P2[tid + 256] = make_uint2(*(uint32_t*)&b0, *(uint32_t*)&b1);
}

// ---------------- conversions / transposes ----------------------------------
__global__ void __launch_bounds__(256)
f2b_k(const float* __restrict__ in, bf16* __restrict__ out, int n4)
{
    int i = blockIdx.x * 256 + threadIdx.x;
    if (i < n4) {
        float4 v = ((const float4*)in)[i];
        ((__nv_bfloat162*)out)[2 * i]     = __floats2bfloat162_rn(v.x, v.y);
        ((__nv_bfloat162*)out)[2 * i + 1] = __floats2bfloat162_rn(v.z, v.w);
    }
}

// fp32 [Kd, Nd] -> bf16 [Nd, Kd]
__global__ void wT_k(const float* __restrict__ in, bf16* __restrict__ out,
                     int Kd, int Nd)
{
    __shared__ float t[32][33];
    int k0 = blockIdx.y * 32, n0 = blockIdx.x * 32;
    int tx = threadIdx.x, ty = threadIdx.y;
#pragma unroll
    for (int i = 0; i < 32; i += 8)
        t[ty + i][tx] = in[(long)(k0 + ty + i) * Nd + n0 + tx];
    __syncthreads();
#pragma unroll
    for (int i = 0; i < 32; i += 8)
        out[(long)(n0 + ty + i) * Kd + k0 + tx] = __float2bfloat16(t[tx][ty + i]);
}

// concat 3 biases [512] -> [1536]
__global__ void bias3_k(const float* __restrict__ b0, const float* __restrict__ b1,
                        const float* __restrict__ b2, float* __restrict__ out)
{
    int i = blockIdx.x * 256 + threadIdx.x;
    if (i < HDIM)          out[i] = b0[i];
    else if (i < 2 * HDIM) out[i] = b1[i - HDIM];
    else                   out[i] = b2[i - 2 * HDIM];
}

// bf16 [L, 3H] slice (offset 2H = psi, ld 1536) -> bf16 [H, L] per batch
__global__ void bT_k(const bf16* __restrict__ in, bf16* __restrict__ out)
{
    __shared__ bf16 t[32][33];
    long ibo = (long)blockIdx.z * LSEQ * 3 * HDIM;
    long obo = (long)blockIdx.z * HDIM * LSEQ;
    int l0 = blockIdx.y * 32, h0 = blockIdx.x * 32;
    int tx = threadIdx.x, ty = threadIdx.y;
#pragma unroll
    for (int i = 0; i < 32; i += 8)
        t[ty + i][tx] = in[ibo + (long)(l0 + ty + i) * (3 * HDIM) + 2 * HDIM + h0 + tx];
    __syncthreads();
#pragma unroll
    for (int i = 0; i < 32; i += 8)
        out[obo + (long)(h0 + ty + i) * LSEQ + l0 + tx] = t[tx][ty + i];
}

// ---------------- launch ----------------------------------------------------
extern "C" void kernel_launch(void* const* d_in, const int* in_sizes, int n_in,
                              void* d_out, int out_size)
{
    const float* x   = (const float*)d_in[0];
    const float* thw = (const float*)d_in[1];
    const float* thb = (const float*)d_in[2];
    const float* phw = (const float*)d_in[3];
    const float* phb = (const float*)d_in[4];
    const float* psw = (const float*)d_in[5];
    const float* psb = (const float*)d_in[6];
    const float* r1w = (const float*)d_in[7];
    const float* r1b = (const float*)d_in[8];
    const float* r2w = (const float*)d_in[9];
    const float* r2b = (const float*)d_in[10];
    float* out = (float*)d_out;

    bf16 *p_xb, *p_wcat, *p_wr1T, *p_wr2T, *p_proj, *p_xpsiT, *p_P, *p_xadd, *p_h1;
    float *p_bcat, *p_S;
    cudaGetSymbolAddress((void**)&p_xb,    g_xb);
    cudaGetSymbolAddress((void**)&p_wcat,  g_wcat);
    cudaGetSymbolAddress((void**)&p_bcat,  g_bcat);
    cudaGetSymbolAddress((void**)&p_wr1T,  g_wr1T);
    cudaGetSymbolAddress((void**)&p_wr2T,  g_wr2T);
    cudaGetSymbolAddress((void**)&p_proj,  g_proj);
    cudaGetSymbolAddress((void**)&p_xpsiT, g_xpsiT);
    cudaGetSymbolAddress((void**)&p_S,     g_S);
    cudaGetSymbolAddress((void**)&p_P,     g_P);
    cudaGetSymbolAddress((void**)&p_xadd,  g_xadd);
    cudaGetSymbolAddress((void**)&p_h1,    g_h1);

    cudaFuncSetAttribute(gemm5<0>, cudaFuncAttributeMaxDynamicSharedMemorySize, GEMM_SMEM);
    cudaFuncSetAttribute(gemm5<2>, cudaFuncAttributeMaxDynamicSharedMemorySize, GEMM_SMEM);
    cudaFuncSetAttribute(gemm5<3>, cudaFuncAttributeMaxDynamicSharedMemorySize, GEMM_SMEM);
    cudaFuncSetAttribute(gemm5<4>, cudaFuncAttributeMaxDynamicSharedMemorySize, GEMM_SMEM);
    cudaFuncSetAttribute(gemm5<5>, cudaFuncAttributeMaxDynamicSharedMemorySize, GEMM_SMEM);

    const int M = NB * LSEQ;                 // 16384
    const int H3 = 3 * HDIM;                 // 1536
    const long sLH3 = (long)LSEQ * H3;
    const long sHL  = (long)HDIM * LSEQ;
    const long sLH  = (long)LSEQ * HDIM;
    const long sLL  = (long)LSEQ * LSEQ;
    dim3 tb(32, 8);

    // launches 1-5 (ncu -s 5 skips these; #6 is the merged projection GEMM)
    f2b_k<<<(M * CDIM / 4 + 255) / 256, 256>>>(x, p_xb, M * CDIM / 4);     // 1
    wT_k<<<dim3(HDIM / 32, CDIM / 32), tb>>>(thw, p_wcat,                  // 2
                                             CDIM, HDIM);
    wT_k<<<dim3(HDIM / 32, CDIM / 32), tb>>>(phw, p_wcat + (size_t)HDIM * CDIM,  // 3
                                             CDIM, HDIM);
    wT_k<<<dim3(HDIM / 32, CDIM / 32), tb>>>(psw, p_wcat + (size_t)2 * HDIM * CDIM, // 4
                                             CDIM, HDIM);
    bias3_k<<<6, 256>>>(thb, phb, psb, p_bcat);                            // 5

    // 6) merged projections: [16384,512] @ [1536,512]^T -> g_proj [16384,1536]
    gemm5<0><<<dim3(H3 / 128, M / 128, 1), 256, GEMM_SMEM>>>(
        p_xb, p_wcat, p_bcat, nullptr, p_proj, CDIM, CDIM, CDIM, H3, 0, 0, 0);

    // 7) transpose psi slice -> [H, L] per batch
    bT_k<<<dim3(HDIM / 32, LSEQ / 32, NB), tb>>>(p_proj, p_xpsiT);

    // 8) logits: S[b] = x_ph @ x_t^T  (both strided slices of g_proj)
    gemm5<2><<<dim3(LSEQ / 128, LSEQ / 128, NB), 256, GEMM_SMEM>>>(
        p_proj + HDIM, p_proj, nullptr, nullptr, p_S,
        HDIM, H3, H3, LSEQ, sLH3, sLH3, sLL);

    // 9) softmax -> bf16 P
    softmax_k<<<NB * LSEQ, 256>>>(p_S, p_P);

    // 10) x_add = P @ x_psi  (Bt = x_psi^T [H, L])
    gemm5<3><<<dim3(HDIM / 128, LSEQ / 128, NB), 256, GEMM_SMEM>>>(
        p_P, p_xpsiT, nullptr, nullptr, p_xadd,
        LSEQ, LSEQ, LSEQ, HDIM, sLL, sHL, sLH);

    // 11-12) MLP weight transposes
    wT_k<<<dim3(CHALF / 32, HDIM / 32), tb>>>(r1w, p_wr1T, HDIM, CHALF);
    wT_k<<<dim3(CDIM / 32, CHALF / 32), tb>>>(r2w, p_wr2T, CHALF, CDIM);

    // 13) h1 = leaky_relu(x_add @ r1w + r1b)
    gemm5<4><<<dim3(CHALF / 128, M / 128, 1), 256, GEMM_SMEM>>>(
        p_xadd, p_wr1T, r1b, nullptr, p_h1, HDIM, HDIM, HDIM, CHALF, 0, 0, 0);

    // 14) out = x + tanh(h1 @ r2w + r2b)
    gemm5<5><<<dim3(CDIM / 128, M / 128, 1), 256, GEMM_SMEM>>>(
        p_h1, p_wr2T, r2b, x, out, CHALF, CHALF, CHALF, CDIM, 0, 0, 0);
}

// round 11
// speedup vs baseline: 1.1668x; 1.1668x over previous
#include <cuda_runtime.h>
#include <cuda_bf16.h>
#include <math.h>
#include <stdint.h>

#define NB 8
#define LSEQ 2048
#define CDIM 512
#define HDIM 512
#define CHALF 256
typedef __nv_bfloat16 bf16;

// ---------------- scratch (device globals: allocation-guard safe) ----------
__device__ __align__(1024) bf16 g_xb   [(size_t)NB * LSEQ * CDIM];
__device__ __align__(1024) bf16 g_wthT [HDIM * CDIM];
__device__ __align__(1024) bf16 g_wphT [HDIM * CDIM];
__device__ __align__(1024) bf16 g_wpsT [HDIM * CDIM];
__device__ __align__(1024) bf16 g_wr1T [CHALF * HDIM];
__device__ __align__(1024) bf16 g_wr2T [CDIM * CHALF];
__device__ __align__(1024) bf16 g_xt   [(size_t)NB * LSEQ * HDIM];
__device__ __align__(1024) bf16 g_xph  [(size_t)NB * LSEQ * HDIM];
__device__ __align__(1024) bf16 g_xpsi [(size_t)NB * LSEQ * HDIM];
__device__ __align__(1024) bf16 g_xpsiT[(size_t)NB * HDIM * LSEQ];
__device__ __align__(1024) float g_S   [(size_t)NB * LSEQ * LSEQ]; // fp32 logits
__device__ __align__(1024) bf16 g_P    [(size_t)NB * LSEQ * LSEQ]; // bf16 attention
__device__ __align__(1024) bf16 g_xadd [(size_t)NB * LSEQ * HDIM];
__device__ __align__(1024) bf16 g_h1   [(size_t)NB * LSEQ * CHALF];

// smem: BK=64 tiles, 128 rows x 144B pitch (72 bf16) = 18432 B per tile stage.
// A stages at 0 / 18432, B stages at 36864 / 55296.
#define TILE_B   18432u
#define B_BASE   36864u
#define GEMM_SMEM 73728

// ---------------- asm helpers ------------------------------------------------
__device__ __forceinline__ void cp16(uint32_t dst, const void* src) {
    asm volatile("cp.async.cg.shared.global [%0], [%1], 16;"
                 :: "r"(dst), "l"(src) : "memory");
}
#define CP_COMMIT() asm volatile("cp.async.commit_group;" ::: "memory")
#define CP_WAIT1()  asm volatile("cp.async.wait_group 1;" ::: "memory")
#define CP_WAIT0()  asm volatile("cp.async.wait_group 0;" ::: "memory")

__device__ __forceinline__ void ldsm4(uint32_t* r, uint32_t addr) {
    asm volatile("ldmatrix.sync.aligned.m8n8.x4.shared.b16 {%0,%1,%2,%3}, [%4];"
                 : "=r"(r[0]), "=r"(r[1]), "=r"(r[2]), "=r"(r[3]) : "r"(addr));
}
__device__ __forceinline__ void mma_bf16(float* c, const uint32_t* a, const uint32_t* b) {
    asm volatile("mma.sync.aligned.m16n8k16.row.col.f32.bf16.bf16.f32 "
                 "{%0,%1,%2,%3},{%4,%5,%6,%7},{%8,%9},{%0,%1,%2,%3};"
                 : "+f"(c[0]), "+f"(c[1]), "+f"(c[2]), "+f"(c[3])
                 : "r"(a[0]), "r"(a[1]), "r"(a[2]), "r"(a[3]), "r"(b[0]), "r"(b[1]));
}

// ---------------- universal bf16 tensor-core GEMM ----------------------------
// C[M,N] = A[M,K] @ Bt[N,K]^T (+bias). Tile 128x128, BK=64, 2-stage cp.async.
// EPI: 0 bias->bf16 | 2 fp32 | 3 bf16 | 4 bias+leaky->bf16 | 5 bias+tanh+res->fp32
template <int EPI>
__global__ void __launch_bounds__(256)
gemm5(const bf16* __restrict__ A, const bf16* __restrict__ Bt,
      const float* __restrict__ bias, const float* __restrict__ res,
      void* __restrict__ Cout, int M, int N, int K, long sA, long sB, long sC)
{
    extern __shared__ __align__(1024) char smem[];
    uint32_t sbase = (uint32_t)__cvta_generic_to_shared(smem);
    const int tid = threadIdx.x, wid = tid >> 5, lane = tid & 31;

    A  += (long)blockIdx.z * sA;
    Bt += (long)blockIdx.z * sB;
    const int m0 = blockIdx.y * 128, n0 = blockIdx.x * 128;

    const int wm = wid >> 2, wn = wid & 3;        // 2x4 warp grid
    const int m_off = wm * 64, n_off = wn * 32;

    float acc[4][4][4];
#pragma unroll
    for (int i = 0; i < 4; i++)
#pragma unroll
        for (int j = 0; j < 4; j++)
#pragma unroll
            for (int u = 0; u < 4; u++) acc[i][j][u] = 0.f;

    const int KT = K >> 6;
    // tile loaders: 128 rows x 128 B (64 bf16); 1024 x 16B chunks; 4 per thread
    auto ldA = [&](int kt, int buf) {
#pragma unroll
        for (int s = 0; s < 4; s++) {
            int ch = s * 256 + tid;
            int r = ch >> 3, seg = ch & 7;
            cp16(sbase + buf * TILE_B + r * 144u + seg * 16u,
                 A + (long)(m0 + r) * K + kt * 64 + seg * 8);
        }
    };
    auto ldB = [&](int kt, int buf) {
#pragma unroll
        for (int s = 0; s < 4; s++) {
            int ch = s * 256 + tid;
            int r = ch >> 3, seg = ch & 7;
            cp16(sbase + B_BASE + buf * TILE_B + r * 144u + seg * 16u,
                 Bt + (long)(n0 + r) * K + kt * 64 + seg * 8);
        }
    };

    ldA(0, 0); ldB(0, 0); CP_COMMIT();

    // ldmatrix lane addressing (constant across k-steps); pitch 72 elements
    const int a_row = m_off + (lane & 15);
    const int a_kof = (lane >> 4) * 8;
    const int b_row = n_off + (lane & 7) + ((lane >> 4) & 1) * 8;
    const int b_kof = ((lane >> 3) & 1) * 8;

    for (int kt = 0; kt < KT; kt++) {
        const int buf = kt & 1;
        if (kt + 1 < KT) {
            ldA(kt + 1, buf ^ 1); ldB(kt + 1, buf ^ 1);
            CP_COMMIT(); CP_WAIT1();
        } else {
            CP_WAIT0();
        }
        __syncthreads();
        const uint32_t Ab = sbase + buf * TILE_B;
        const uint32_t Bb = sbase + B_BASE + buf * TILE_B;
#pragma unroll
        for (int kk = 0; kk < 64; kk += 16) {
            uint32_t a[4][4], bq[2][4];
#pragma unroll
            for (int mt = 0; mt < 4; mt++)
                ldsm4(a[mt], Ab + ((a_row + mt * 16) * 72 + kk + a_kof) * 2);
#pragma unroll
            for (int p = 0; p < 2; p++)
                ldsm4(bq[p], Bb + ((b_row + p * 16) * 72 + kk + b_kof) * 2);
#pragma unroll
            for (int mt = 0; mt < 4; mt++)
#pragma unroll
                for (int nt = 0; nt < 4; nt++)
                    mma_bf16(acc[mt][nt], a[mt], &bq[nt >> 1][(nt & 1) * 2]);
        }
        __syncthreads();
    }

    // ---- epilogue ----
    const int l4 = lane >> 2, l2 = (lane & 3) * 2;
#pragma unroll
    for (int mt = 0; mt < 4; mt++) {
#pragma unroll
        for (int nt = 0; nt < 4; nt++) {
            int row = m0 + m_off + mt * 16 + l4;
            int col = n0 + n_off + nt * 8 + l2;
            float c0 = acc[mt][nt][0], c1 = acc[mt][nt][1];
            float c2 = acc[mt][nt][2], c3 = acc[mt][nt][3];
            if (EPI == 0 || EPI == 4 || EPI == 5) {
                float b0 = bias[col], b1 = bias[col + 1];
                c0 += b0; c1 += b1; c2 += b0; c3 += b1;
            }
            if (EPI == 4) {
                c0 = fmaxf(c0, 0.2f * c0); c1 = fmaxf(c1, 0.2f * c1);
                c2 = fmaxf(c2, 0.2f * c2); c3 = fmaxf(c3, 0.2f * c3);
            }
            if (EPI == 5) {
                const float2 r0 = *(const float2*)(res + (long)row * N + col);
                const float2 r1 = *(const float2*)(res + (long)(row + 8) * N + col);
                c0 = tanhf(c0) + r0.x; c1 = tanhf(c1) + r0.y;
                c2 = tanhf(c2) + r1.x; c3 = tanhf(c3) + r1.y;
            }
            if (EPI == 2 || EPI == 5) {
                float* Cf = (float*)Cout + (long)blockIdx.z * sC;
                *(float2*)(Cf + (long)row * N + col)       = make_float2(c0, c1);
                *(float2*)(Cf + (long)(row + 8) * N + col) = make_float2(c2, c3);
            } else {
                bf16* Cb = (bf16*)Cout + (long)blockIdx.z * sC;
                *(__nv_bfloat162*)(Cb + (long)row * N + col)       = __floats2bfloat162_rn(c0, c1);
                *(__nv_bfloat162*)(Cb + (long)(row + 8) * N + col) = __floats2bfloat162_rn(c2, c3);
            }
        }
    }
}

// ---------------- softmax: fp32 in -> bf16 out ------------------------------
__global__ void __launch_bounds__(256)
softmax_k(const float* __restrict__ S, bf16* __restrict__ P)
{
    long base = (long)blockIdx.x * LSEQ;
    const float4* S4 = (const float4*)(S + base);
    int tid = threadIdx.x;
    __shared__ float red[256];

    float4 v0 = S4[tid], v1 = S4[tid + 256];
    float m = fmaxf(fmaxf(fmaxf(v0.x, v0.y), fmaxf(v0.z, v0.w)),
                    fmaxf(fmaxf(v1.x, v1.y), fmaxf(v1.z, v1.w)));
    red[tid] = m;
    __syncthreads();
    for (int s = 128; s > 0; s >>= 1) {
        if (tid < s) red[tid] = fmaxf(red[tid], red[tid + s]);
        __syncthreads();
    }
    m = red[0];
    __syncthreads();

    v0.x = __expf(v0.x - m); v0.y = __expf(v0.y - m);
    v0.z = __expf(v0.z - m); v0.w = __expf(v0.w - m);
    v1.x = __expf(v1.x - m); v1.y = __expf(v1.y - m);
    v1.z = __expf(v1.z - m); v1.w = __expf(v1.w - m);
    float sum = (v0.x + v0.y + v0.z + v0.w) + (v1.x + v1.y + v1.z + v1.w);
    red[tid] = sum;
    __syncthreads();
    for (int s = 128; s > 0; s >>= 1) {
        if (tid < s) red[tid] += red[tid + s];
        __syncthreads();
    }
    float inv = 1.f / red[0];

    uint2* P2 = (uint2*)(P + base);
    __nv_bfloat162 a0 = __floats2bfloat162_rn(v0.x * inv, v0.y * inv);
    __nv_bfloat162 a1 = __floats2bfloat162_rn(v0.z * inv, v0.w * inv);
    __nv_bfloat162 b0 = __floats2bfloat162_rn(v1.x * inv, v1.y * inv);
    __nv_bfloat162 b1 = __floats2bfloat162_rn(v1.z * inv, v1.w * inv);
    P2[tid]       = make_uint2(*(uint32_t*)&a0, *(uint32_t*)&a1);
    P2[tid + 256] = make_uint2(*(uint32_t*)&b0, *(uint32_t*)&b1);
}

// ---------------- conversions / transposes ----------------------------------
__global__ void __launch_bounds__(256)
f2b_k(const float* __restrict__ in, bf16* __restrict__ out, int n4)
{
    int i = blockIdx.x * 256 + threadIdx.x;
    if (i < n4) {
        float4 v = ((const float4*)in)[i];
        ((__nv_bfloat162*)out)[2 * i]     = __floats2bfloat162_rn(v.x, v.y);
        ((__nv_bfloat162*)out)[2 * i + 1] = __floats2bfloat162_rn(v.z, v.w);
    }
}

// fp32 [Kd, Nd] -> bf16 [Nd, Kd]
__global__ void wT_k(const float* __restrict__ in, bf16* __restrict__ out,
                     int Kd, int Nd)
{
    __shared__ float t[32][33];
    int k0 = blockIdx.y * 32, n0 = blockIdx.x * 32;
    int tx = threadIdx.x, ty = threadIdx.y;
#pragma unroll
    for (int i = 0; i < 32; i += 8)
        t[ty + i][tx] = in[(long)(k0 + ty + i) * Nd + n0 + tx];
    __syncthreads();
#pragma unroll
    for (int i = 0; i < 32; i += 8)
        out[(long)(n0 + ty + i) * Kd + k0 + tx] = __float2bfloat16(t[tx][ty + i]);
}

// bf16 [L, H] -> bf16 [H, L] per batch
__global__ void bT_k(const bf16* __restrict__ in, bf16* __restrict__ out)
{
    __shared__ bf16 t[32][33];
    long boff = (long)blockIdx.z * LSEQ * HDIM;
    int l0 = blockIdx.y * 32, h0 = blockIdx.x * 32;
    int tx = threadIdx.x, ty = threadIdx.y;
#pragma unroll
    for (int i = 0; i < 32; i += 8)
        t[ty + i][tx] = in[boff + (long)(l0 + ty + i) * HDIM + h0 + tx];
    __syncthreads();
#pragma unroll
    for (int i = 0; i < 32; i += 8)
        out[boff + (long)(h0 + ty + i) * LSEQ + l0 + tx] = t[tx][ty + i];
}

// ---------------- launch ----------------------------------------------------
extern "C" void kernel_launch(void* const* d_in, const int* in_sizes, int n_in,
                              void* d_out, int out_size)
{
    const float* x   = (const float*)d_in[0];
    const float* thw = (const float*)d_in[1];
    const float* thb = (const float*)d_in[2];
    const float* phw = (const float*)d_in[3];
    const float* phb = (const float*)d_in[4];
    const float* psw = (const float*)d_in[5];
    const float* psb = (const float*)d_in[6];
    const float* r1w = (const float*)d_in[7];
    const float* r1b = (const float*)d_in[8];
    const float* r2w = (const float*)d_in[9];
    const float* r2b = (const float*)d_in[10];
    float* out = (float*)d_out;

    bf16 *p_xb, *p_wthT, *p_wphT, *p_wpsT, *p_wr1T, *p_wr2T;
    bf16 *p_xt, *p_xph, *p_xpsi, *p_xpsiT, *p_P, *p_xadd, *p_h1;
    float *p_S;
    cudaGetSymbolAddress((void**)&p_xb,    g_xb);
    cudaGetSymbolAddress((void**)&p_wthT,  g_wthT);
    cudaGetSymbolAddress((void**)&p_wphT,  g_wphT);
    cudaGetSymbolAddress((void**)&p_wpsT,  g_wpsT);
    cudaGetSymbolAddress((void**)&p_wr1T,  g_wr1T);
    cudaGetSymbolAddress((void**)&p_wr2T,  g_wr2T);
    cudaGetSymbolAddress((void**)&p_xt,    g_xt);
    cudaGetSymbolAddress((void**)&p_xph,   g_xph);
    cudaGetSymbolAddress((void**)&p_xpsi,  g_xpsi);
    cudaGetSymbolAddress((void**)&p_xpsiT, g_xpsiT);
    cudaGetSymbolAddress((void**)&p_S,     g_S);
    cudaGetSymbolAddress((void**)&p_P,     g_P);
    cudaGetSymbolAddress((void**)&p_xadd,  g_xadd);
    cudaGetSymbolAddress((void**)&p_h1,    g_h1);

    cudaFuncSetAttribute(gemm5<0>, cudaFuncAttributeMaxDynamicSharedMemorySize, GEMM_SMEM);
    cudaFuncSetAttribute(gemm5<2>, cudaFuncAttributeMaxDynamicSharedMemorySize, GEMM_SMEM);
    cudaFuncSetAttribute(gemm5<3>, cudaFuncAttributeMaxDynamicSharedMemorySize, GEMM_SMEM);
    cudaFuncSetAttribute(gemm5<4>, cudaFuncAttributeMaxDynamicSharedMemorySize, GEMM_SMEM);
    cudaFuncSetAttribute(gemm5<5>, cudaFuncAttributeMaxDynamicSharedMemorySize, GEMM_SMEM);

    const int M = NB * LSEQ;                 // 16384
    const long sLH = (long)LSEQ * HDIM;
    const long sHL = (long)HDIM * LSEQ;
    const long sLL = (long)LSEQ * LSEQ;
    dim3 tb(32, 8);

    // 0) convert inputs
    f2b_k<<<(M * CDIM / 4 + 255) / 256, 256>>>(x, p_xb, M * CDIM / 4);
    wT_k<<<dim3(HDIM / 32, CDIM / 32), tb>>>(thw, p_wthT, CDIM, HDIM);
    wT_k<<<dim3(HDIM / 32, CDIM / 32), tb>>>(phw, p_wphT, CDIM, HDIM);
    wT_k<<<dim3(HDIM / 32, CDIM / 32), tb>>>(psw, p_wpsT, CDIM, HDIM);
    wT_k<<<dim3(CHALF / 32, HDIM / 32), tb>>>(r1w, p_wr1T, HDIM, CHALF);
    wT_k<<<dim3(CDIM / 32, CHALF / 32), tb>>>(r2w, p_wr2T, CHALF, CDIM);

    // 1) projections
    {
        dim3 g(HDIM / 128, M / 128, 1);
        gemm5<0><<<g, 256, GEMM_SMEM>>>(p_xb, p_wthT, thb, nullptr, p_xt,
                                        M, HDIM, CDIM, 0, 0, 0);
        gemm5<0><<<g, 256, GEMM_SMEM>>>(p_xb, p_wphT, phb, nullptr, p_xph,
                                        M, HDIM, CDIM, 0, 0, 0);
        gemm5<0><<<g, 256, GEMM_SMEM>>>(p_xb, p_wpsT, psb, nullptr, p_xpsi,
                                        M, HDIM, CDIM, 0, 0, 0);
    }

    // 1b) transpose psi per batch -> [H, L]
    bT_k<<<dim3(HDIM / 32, LSEQ / 32, NB), tb>>>(p_xpsi, p_xpsiT);

    // 2) logits (fp32 out)
    gemm5<2><<<dim3(LSEQ / 128, LSEQ / 128, NB), 256, GEMM_SMEM>>>(
        p_xph, p_xt, nullptr, nullptr, p_S, LSEQ, LSEQ, HDIM, sLH, sLH, sLL);

    // 3) softmax -> bf16 P
    softmax_k<<<NB * LSEQ, 256>>>(p_S, p_P);

    // 4) x_add = P @ x_psi  (Bt = x_psi^T [H, L])
    gemm5<3><<<dim3(HDIM / 128, LSEQ / 128, NB), 256, GEMM_SMEM>>>(
        p_P, p_xpsiT, nullptr, nullptr, p_xadd, LSEQ, HDIM, LSEQ, sLL, sHL, sLH);

    // 5) h1 = leaky_relu(x_add @ r1w + r1b)
    gemm5<4><<<dim3(CHALF / 128, M / 128, 1), 256, GEMM_SMEM>>>(
        p_xadd, p_wr1T, r1b, nullptr, p_h1, M, CHALF, HDIM, 0, 0, 0);

    // 6) out = x + tanh(h1 @ r2w + r2b)
    gemm5<5><<<dim3(CDIM / 128, M / 128, 1), 256, GEMM_SMEM>>>(
        p_h1, p_wr2T, r2b, x, out, M, CDIM, CHALF, 0, 0, 0);
}